// round 11
// baseline (speedup 1.0000x reference)
#include <cuda_runtime.h>
#include <cuda_fp16.h>
#include <math.h>
#include <stdint.h>

#define B_DIM 16384
#define S_DIM 64
#define A_DIM 16
#define H_DIM 256
#define E_DIM 8
#define K_CAT 2048   // E * H
#define N_G   1024   // S*A
#define N_F   64

// scratch (all fp16 operands)
__device__ __half g_H[(size_t)B_DIM * K_CAT];            // Hcat, 67 MB
__device__ __half g_WgT[(size_t)N_G * K_CAT];            // Wg^T [n][k]
__device__ __half g_WfT[(size_t)N_F * K_CAT];            // Wf^T [n][k]
__device__ __half g_W1T[(size_t)E_DIM * H_DIM * S_DIM];  // [e][h][s]
__device__ __half g_W2T[(size_t)E_DIM * H_DIM * H_DIM];  // [e][hout][hin]
__device__ float  g_bsum[N_G + N_F];                     // sum_e bias (fp32)

// ---------------------------------------------------------------- helpers
__device__ __forceinline__ uint32_t s2u(const void* p) {
    return (uint32_t)__cvta_generic_to_shared(p);
}
__device__ __forceinline__ void cp16(void* dst, const void* src) {
    asm volatile("cp.async.cg.shared.global [%0], [%1], 16;"
                 :: "r"(s2u(dst)), "l"(src));
}
__device__ __forceinline__ void cp_commit() { asm volatile("cp.async.commit_group;"); }
template<int N> __device__ __forceinline__ void cp_wait() {
    asm volatile("cp.async.wait_group %0;" :: "n"(N));
}
__device__ __forceinline__ void ldsm4(uint32_t* r, uint32_t addr) {
    asm volatile("ldmatrix.sync.aligned.m8n8.x4.shared.b16 {%0,%1,%2,%3}, [%4];"
                 : "=r"(r[0]), "=r"(r[1]), "=r"(r[2]), "=r"(r[3]) : "r"(addr));
}
// fp32-accumulate m16n8k16 (the proven fast path on this chip)
__device__ __forceinline__ void mma_f16(float* d, const uint32_t* a, const uint32_t* b) {
    asm volatile(
        "mma.sync.aligned.m16n8k16.row.col.f32.f16.f16.f32 "
        "{%0,%1,%2,%3},{%4,%5,%6,%7},{%8,%9},{%0,%1,%2,%3};"
        : "+f"(d[0]), "+f"(d[1]), "+f"(d[2]), "+f"(d[3])
        : "r"(a[0]), "r"(a[1]), "r"(a[2]), "r"(a[3]), "r"(b[0]), "r"(b[1]));
}

// 32x32 transpose tile, 256 threads (32x8)
__device__ __forceinline__ void tr_tile256(const float* __restrict__ W,
                                           __half* __restrict__ WT,
                                           int K, int N, int kt, int nt, int tid) {
    __shared__ float t[32][33];
    int x = tid & 31, y = tid >> 5;
    int k0 = kt * 32, n0 = nt * 32;
    #pragma unroll
    for (int i = 0; i < 32; i += 8)
        t[y + i][x] = W[(size_t)(k0 + y + i) * N + n0 + x];
    __syncthreads();
    #pragma unroll
    for (int i = 0; i < 32; i += 8)
        WT[(size_t)(n0 + y + i) * K + k0 + x] = __float2half_rn(t[x][y + i]);
}

// 32x32 transpose tile, 128 threads (32x4)
__device__ __forceinline__ void tr_tile128(const float* __restrict__ W,
                                           __half* __restrict__ WT,
                                           int K, int N, int kt, int nt, int tid) {
    __shared__ float t[32][33];
    int x = tid & 31, y = tid >> 5;   // y in 0..3
    int k0 = kt * 32, n0 = nt * 32;
    #pragma unroll
    for (int i = 0; i < 32; i += 4)
        t[y + i][x] = W[(size_t)(k0 + y + i) * N + n0 + x];
    __syncthreads();
    #pragma unroll
    for (int i = 0; i < 32; i += 4)
        WT[(size_t)(n0 + y + i) * K + k0 + x] = __float2half_rn(t[x][y + i]);
}

// ---------------------------------------------------------------------------
// Serial prep: ONLY what k_mlp needs (W1T, W2T). 640 blocks.
// Blocks 0..127:   W1 per-e [64,256]  -> W1T  (e = t>>4; tile t&15: 2x8)
// Blocks 128..639: W2 per-e [256,256] -> W2T  (e = t>>6; tile t&63: 8x8)
// ---------------------------------------------------------------------------
__global__ void __launch_bounds__(256) k_prep(
    const float* __restrict__ W1, const float* __restrict__ W2)
{
    const int id = blockIdx.x, tid = threadIdx.x;
    if (id < 128) {
        int e = id >> 4, t = id & 15;
        tr_tile256(W1 + (size_t)e * S_DIM * H_DIM,
                   g_W1T + (size_t)e * S_DIM * H_DIM,
                   S_DIM, H_DIM, t & 1, t >> 1, tid);
    } else {
        int t = id - 128;
        int e = t >> 6; t &= 63;
        tr_tile256(W2 + (size_t)e * H_DIM * H_DIM,
                   g_W2T + (size_t)e * H_DIM * H_DIM,
                   H_DIM, H_DIM, t & 7, t >> 3, tid);
    }
}

// ---------------------------------------------------------------------------
// Pass 1 + folded aux prep. Grid 4233 x 1 (1D):
//   id < 4096, even  -> mlp task m=id>>1  (b0=(m>>3)*64, e=m&7)   [2048 tasks]
//   id < 4096, odd   -> aux task a=id>>1                            [2048 tasks]
//   id >= 4096       -> aux task a=2048+(id-4096)                   [137 tasks]
// aux: a<2048 Wg transpose; a<2176 Wf transpose; else bias sums (9 blocks).
// mlp CTA: converts its own state tile f32->f16, then round-8 MLP.
// ---------------------------------------------------------------------------
__global__ void __launch_bounds__(128, 2) k_mlp(
    const float* __restrict__ state,
    const float* __restrict__ b1, const float* __restrict__ b2,
    const float* __restrict__ Wg, const float* __restrict__ Wf,
    const float* __restrict__ bg, const float* __restrict__ bf)
{
    const int id = blockIdx.x, tid = threadIdx.x;
    int mtask = -1, atask = -1;
    if (id < 4096) { if (id & 1) atask = id >> 1; else mtask = id >> 1; }
    else atask = 2048 + (id - 4096);

    if (atask >= 0) {
        if (atask < 2048) {
            tr_tile128(Wg, g_WgT, K_CAT, N_G, atask & 63, atask >> 6, tid);
        } else if (atask < 2176) {
            int t = atask - 2048;
            tr_tile128(Wf, g_WfT, K_CAT, N_F, t & 63, t >> 6, tid);
        } else {
            int q = (atask - 2176) * 128 + tid;
            if (q < N_G) {
                float s = 0.f;
                #pragma unroll
                for (int e = 0; e < E_DIM; ++e) s += bg[(size_t)e * N_G + q];
                g_bsum[q] = s;
            } else if (q < N_G + N_F) {
                int qq = q - N_G;
                float s = 0.f;
                #pragma unroll
                for (int e = 0; e < E_DIM; ++e) s += bf[(size_t)e * N_F + qq];
                g_bsum[q] = s;
            }
        }
        return;
    }

    extern __shared__ __half smh[];
    __half* sS   = smh;                  // [64][72] phase 1
    __half* sW1  = smh + 64 * 72;        // [256][72] phase 1
    __half* sH   = smh;                  // [64][264] phase 2 (aliases sS/sW1)
    __half* sW2a = smh + 23040;          // [256][40]
    __half* sW2b = sW2a + 256 * 40;      // [256][40]
    float*  sSf  = (float*)(smh + 23040 + 2 * 256 * 40);  // [64][64] f32 state

    const int lane = tid & 31, wn = tid >> 5;
    const int g = lane >> 2, tg = lane & 3;
    const int mi = lane >> 3, ri = lane & 7;
    const int b0 = (mtask >> 3) * 64;
    const int e  = mtask & 7;

    const __half* W1e = g_W1T + (size_t)e * H_DIM * S_DIM;
    const __half* W2e = g_W2T + (size_t)e * H_DIM * H_DIM;

    auto loadW2 = [&](__half* buf, int kc) {
        #pragma unroll
        for (int j = 0; j < 8; ++j) {
            int lin = j * 128 + tid, row = lin >> 2, seg = lin & 3;
            cp16(buf + row * 40 + seg * 8, W2e + (size_t)row * 256 + kc * 32 + seg * 8);
        }
    };

    // state f32 tile (64 x 64 f32 = 16 KB), W1T f16
    #pragma unroll
    for (int j = 0; j < 8; ++j) {
        int lin = j * 128 + tid, row = lin >> 4, seg = lin & 15;
        cp16(sSf + row * 64 + seg * 4, state + (size_t)(b0 + row) * S_DIM + seg * 4);
    }
    #pragma unroll
    for (int j = 0; j < 16; ++j) {
        int lin = j * 128 + tid, row = lin >> 3, seg = lin & 7;
        cp16(sW1 + row * 72 + seg * 8, W1e + (size_t)row * S_DIM + seg * 8);
    }
    cp_commit();
    loadW2(sW2a, 0); cp_commit();
    loadW2(sW2b, 1); cp_commit();
    cp_wait<2>(); __syncthreads();

    // convert state f32 -> f16 into sS [64][72]
    #pragma unroll
    for (int j = 0; j < 16; ++j) {
        int idx = j * 128 + tid;            // pair index, 2048 pairs
        int row = idx >> 5, col2 = idx & 31;
        float2 v = *(const float2*)(sSf + row * 64 + col2 * 2);
        *(__half2*)(sS + row * 72 + col2 * 2) = __floats2half2_rn(v.x, v.y);
    }
    __syncthreads();

    const uint32_t uS = s2u(sS), uW1 = s2u(sW1);
    const uint32_t uH = s2u(sH), uW2 = s2u(sW2a);
    uint32_t aoff72[4], aoff264[4], boff72[4], boff40[4];
    #pragma unroll
    for (int t = 0; t < 4; ++t) {
        int rrow = t * 16 + ri + (mi & 1) * 8;
        int kadd = (mi >> 1) * 8;
        aoff72[t]  = (uint32_t)(rrow * 72  + kadd) * 2;
        aoff264[t] = (uint32_t)(rrow * 264 + kadd) * 2;
    }
    #pragma unroll
    for (int j = 0; j < 4; ++j) {
        int nrow = wn * 64 + (j * 2 + (lane >> 4)) * 8 + ri;
        int kadd = ((lane >> 3) & 1) * 8;
        boff72[j] = (uint32_t)(nrow * 72 + kadd) * 2;
        boff40[j] = (uint32_t)(nrow * 40 + kadd) * 2;
    }

    float acc[4][8][4];
    #pragma unroll
    for (int t = 0; t < 4; ++t)
        #pragma unroll
        for (int u = 0; u < 8; ++u)
            #pragma unroll
            for (int v = 0; v < 4; ++v) acc[t][u][v] = 0.f;

    #pragma unroll
    for (int ks = 0; ks < 4; ++ks) {
        uint32_t a[4][4], b[8][2];
        #pragma unroll
        for (int t = 0; t < 4; ++t) ldsm4(a[t], uS + aoff72[t] + ks * 32);
        #pragma unroll
        for (int j = 0; j < 4; ++j) {
            uint32_t r[4];
            ldsm4(r, uW1 + boff72[j] + ks * 32);
            b[2*j][0] = r[0]; b[2*j][1] = r[1];
            b[2*j+1][0] = r[2]; b[2*j+1][1] = r[3];
        }
        #pragma unroll
        for (int t = 0; t < 4; ++t)
            #pragma unroll
            for (int u = 0; u < 8; ++u)
                mma_f16(acc[t][u], a[t], b[u]);
    }
    __syncthreads();

    #pragma unroll
    for (int t = 0; t < 4; ++t) {
        int r = t * 16 + g;
        #pragma unroll
        for (int u = 0; u < 8; ++u) {
            int cl = wn * 64 + u * 8 + tg * 2;
            float bb0 = b1[(size_t)e * H_DIM + cl];
            float bb1 = b1[(size_t)e * H_DIM + cl + 1];
            __half2 v0 = __floats2half2_rn(tanhf(acc[t][u][0] + bb0),
                                           tanhf(acc[t][u][1] + bb1));
            __half2 v1 = __floats2half2_rn(tanhf(acc[t][u][2] + bb0),
                                           tanhf(acc[t][u][3] + bb1));
            *(__half2*)(sH + r * 264 + cl)       = v0;
            *(__half2*)(sH + (r + 8) * 264 + cl) = v1;
        }
    }
    __syncthreads();

    #pragma unroll
    for (int t = 0; t < 4; ++t)
        #pragma unroll
        for (int u = 0; u < 8; ++u)
            #pragma unroll
            for (int v = 0; v < 4; ++v) acc[t][u][v] = 0.f;

    for (int kc = 0; kc < 8; ++kc) {
        if (kc < 7) cp_wait<1>(); else cp_wait<0>();
        __syncthreads();
        const uint32_t stB = uW2 + (uint32_t)(kc & 1) * (256 * 40 * 2);
        #pragma unroll
        for (int ks = 0; ks < 2; ++ks) {
            const uint32_t kbyteA = (uint32_t)(kc * 32 + ks * 16) * 2;
            uint32_t a[4][4], b[8][2];
            #pragma unroll
            for (int t = 0; t < 4; ++t) ldsm4(a[t], uH + aoff264[t] + kbyteA);
            #pragma unroll
            for (int j = 0; j < 4; ++j) {
                uint32_t r[4];
                ldsm4(r, stB + boff40[j] + ks * 32);
                b[2*j][0] = r[0]; b[2*j][1] = r[1];
                b[2*j+1][0] = r[2]; b[2*j+1][1] = r[3];
            }
            #pragma unroll
            for (int t = 0; t < 4; ++t)
                #pragma unroll
                for (int u = 0; u < 8; ++u)
                    mma_f16(acc[t][u], a[t], b[u]);
        }
        __syncthreads();
        if (kc + 2 < 8) {
            loadW2((kc & 1) ? sW2b : sW2a, kc + 2);
            cp_commit();
        }
    }

    #pragma unroll
    for (int t = 0; t < 4; ++t) {
        size_t r = (size_t)b0 + t * 16 + g;
        #pragma unroll
        for (int u = 0; u < 8; ++u) {
            int cl = wn * 64 + u * 8 + tg * 2;
            float bb0 = b2[(size_t)e * H_DIM + cl];
            float bb1 = b2[(size_t)e * H_DIM + cl + 1];
            __half2 v0 = __floats2half2_rn(tanhf(acc[t][u][0] + bb0),
                                           tanhf(acc[t][u][1] + bb1));
            __half2 v1 = __floats2half2_rn(tanhf(acc[t][u][2] + bb0),
                                           tanhf(acc[t][u][3] + bb1));
            __half* dst = g_H + r * K_CAT + e * H_DIM + cl;
            *(__half2*)dst = v0;
            *(__half2*)(dst + 8 * K_CAT) = v1;
        }
    }
}

// ---------------------------------------------------------------------------
// Pass 2 tile worker (round-8 proven): fp32-acc HMMA, 3-stage cp.async,
// one __syncthreads per K-chunk.
// ---------------------------------------------------------------------------
template<int NT>
__device__ __forceinline__ void gemm_tile(
    const __half* __restrict__ Abase, const __half* __restrict__ Bbase,
    const float* __restrict__ bsumN, float* __restrict__ outBase, int Ntot,
    __half* smh, int tid)
{
    constexpr int TN  = NT * 16;
    constexpr int NCH = K_CAT / 64;

    __half* sA = smh;
    __half* sB = smh + 3 * 128 * 72;
    float*  sBias = (float*)(sB + 3 * TN * 72);

    const int lane = tid & 31, w = tid >> 5;
    const int wm = w >> 1, wn = w & 1;
    const int g = lane >> 2, tg = lane & 3;
    const int mi = lane >> 3, ri = lane & 7;

    if (tid < TN) sBias[tid] = bsumN[tid];

    auto loadA = [&](int stage, int kc) {
        __half* buf = sA + stage * (128 * 72);
        #pragma unroll
        for (int j = 0; j < 8; ++j) {
            int lin = j * 128 + tid, row = lin >> 3, seg = lin & 7;
            cp16(buf + row * 72 + seg * 8, Abase + (size_t)row * K_CAT + kc * 64 + seg * 8);
        }
    };
    auto loadB = [&](int stage, int kc) {
        __half* buf = sB + stage * (TN * 72);
        #pragma unroll
        for (int j = 0; j < TN / 16; ++j) {
            int lin = j * 128 + tid, row = lin >> 3, seg = lin & 7;
            cp16(buf + row * 72 + seg * 8, Bbase + (size_t)row * K_CAT + kc * 64 + seg * 8);
        }
    };

    const uint32_t uA = s2u(sA), uB = s2u(sB);
    uint32_t aoff[4], boff[NT / 2];
    #pragma unroll
    for (int t = 0; t < 4; ++t)
        aoff[t] = (uint32_t)((wm * 64 + t * 16 + ri + (mi & 1) * 8) * 72 +
                             (mi >> 1) * 8) * 2;
    #pragma unroll
    for (int j = 0; j < NT / 2; ++j)
        boff[j] = (uint32_t)((wn * (TN / 2) + (j * 2 + (lane >> 4)) * 8 + ri) * 72 +
                             ((lane >> 3) & 1) * 8) * 2;

    float acc[4][NT][4];
    #pragma unroll
    for (int t = 0; t < 4; ++t)
        #pragma unroll
        for (int u = 0; u < NT; ++u)
            #pragma unroll
            for (int v = 0; v < 4; ++v) acc[t][u][v] = 0.f;

    loadA(0, 0); loadB(0, 0); cp_commit();
    loadA(1, 1); loadB(1, 1); cp_commit();

    for (int kc = 0; kc < NCH; ++kc) {
        if (kc + 1 < NCH) cp_wait<1>(); else cp_wait<0>();
        __syncthreads();
        if (kc + 2 < NCH) {
            loadA((kc + 2) % 3, kc + 2);
            loadB((kc + 2) % 3, kc + 2);
            cp_commit();
        }
        const int stage = kc % 3;
        const uint32_t stA = uA + (uint32_t)stage * (128 * 72 * 2);
        const uint32_t stB = uB + (uint32_t)stage * (TN * 72 * 2);

        #pragma unroll
        for (int ks = 0; ks < 4; ++ks) {
            uint32_t a[4][4], b[NT][2];
            #pragma unroll
            for (int t = 0; t < 4; ++t) ldsm4(a[t], stA + aoff[t] + ks * 32);
            #pragma unroll
            for (int j = 0; j < NT / 2; ++j) {
                uint32_t r[4];
                ldsm4(r, stB + boff[j] + ks * 32);
                b[2*j][0] = r[0]; b[2*j][1] = r[1];
                b[2*j+1][0] = r[2]; b[2*j+1][1] = r[3];
            }
            #pragma unroll
            for (int t = 0; t < 4; ++t)
                #pragma unroll
                for (int u = 0; u < NT; ++u)
                    mma_f16(acc[t][u], a[t], b[u]);
        }
    }

    #pragma unroll
    for (int t = 0; t < 4; ++t) {
        size_t r0 = wm * 64 + t * 16 + g;
        #pragma unroll
        for (int u = 0; u < NT; ++u) {
            int cl = wn * (TN / 2) + u * 8 + tg * 2;
            float bs0 = sBias[cl], bs1 = sBias[cl + 1];
            float2 v0, v1;
            v0.x = 0.125f * (acc[t][u][0] + bs0);
            v0.y = 0.125f * (acc[t][u][1] + bs1);
            v1.x = 0.125f * (acc[t][u][2] + bs0);
            v1.y = 0.125f * (acc[t][u][3] + bs1);
            *(float2*)(outBase + r0 * Ntot + cl)       = v0;
            *(float2*)(outBase + (r0 + 8) * Ntot + cl) = v1;
        }
    }
}

// Merged output GEMM, round-8 ordering: g tiles ids 0..1023, f tiles last.
__global__ void __launch_bounds__(128, 2) k_out(
    float* __restrict__ out_f, float* __restrict__ out_g)
{
    extern __shared__ __half smh[];
    const int id = blockIdx.x, tid = threadIdx.x;
    if (id < 1024) {
        const int bm = id & 127, bn = id >> 7;
        gemm_tile<8>(g_H + (size_t)bm * 128 * K_CAT,
                     g_WgT + (size_t)bn * 128 * K_CAT,
                     g_bsum + bn * 128,
                     out_g + (size_t)bm * 128 * N_G + bn * 128,
                     N_G, smh, tid);
    } else {
        const int bm = id - 1024;
        gemm_tile<4>(g_H + (size_t)bm * 128 * K_CAT,
                     g_WfT,
                     g_bsum + N_G,
                     out_f + (size_t)bm * 128 * N_F,
                     N_F, smh, tid);
    }
}

// ---------------------------------------------------------------------------
extern "C" void kernel_launch(void* const* d_in, const int* in_sizes, int n_in,
                              void* d_out, int out_size)
{
    const float* state = (const float*)d_in[0];
    const float* W1    = (const float*)d_in[1];
    const float* b1    = (const float*)d_in[2];
    const float* W2    = (const float*)d_in[3];
    const float* b2    = (const float*)d_in[4];
    const float* Wf    = (const float*)d_in[5];
    const float* bf    = (const float*)d_in[6];
    const float* Wg    = (const float*)d_in[7];
    const float* bg    = (const float*)d_in[8];

    float* out   = (float*)d_out;
    float* out_f = out;                              // f_mean [B, 64]
    float* out_g = out + (size_t)B_DIM * S_DIM;      // g_mean [B, 1024]

    // k_mlp smem: 23040 halves (phase1/phase2) + 2x256x40 halves (W2 bufs)
    //             + 64x64 f32 state tile
    const int smemM = 23040 * 2 + 2 * 256 * 40 * 2 + 64 * 64 * 4;  // 103,424 B
    const int smemO = (3 * 128 * 72 + 3 * 128 * 72) * 2 + 512;     // 111,104 B

    cudaFuncSetAttribute(k_mlp, cudaFuncAttributeMaxDynamicSharedMemorySize, smemM);
    cudaFuncSetAttribute(k_out, cudaFuncAttributeMaxDynamicSharedMemorySize, smemO);

    k_prep<<<640, 256>>>(W1, W2);
    k_mlp<<<4233, 128, smemM>>>(state, b1, b2, Wg, Wf, bg, bf);
    k_out<<<1152, 128, smemO>>>(out_f, out_g);
}

// round 12
// speedup vs baseline: 1.0444x; 1.0444x over previous
#include <cuda_runtime.h>
#include <cuda_fp16.h>
#include <math.h>
#include <stdint.h>

#define B_DIM 16384
#define S_DIM 64
#define A_DIM 16
#define H_DIM 256
#define E_DIM 8
#define K_CAT 2048   // E * H
#define N_G   1024   // S*A
#define N_F   64

// scratch (all fp16 operands)
__device__ __half g_H[(size_t)B_DIM * K_CAT];            // Hcat, 67 MB
__device__ __half g_Sh[(size_t)B_DIM * S_DIM];           // state fp16
__device__ __half g_WgT[(size_t)N_G * K_CAT];            // Wg^T [n][k]
__device__ __half g_WfT[(size_t)N_F * K_CAT];            // Wf^T [n][k]
__device__ __half g_W1T[(size_t)E_DIM * H_DIM * S_DIM];  // [e][h][s]
__device__ __half g_W2T[(size_t)E_DIM * H_DIM * H_DIM];  // [e][hout][hin]
__device__ float  g_bsum[N_G + N_F];                     // sum_e bias (fp32)

// ---------------------------------------------------------------- helpers
__device__ __forceinline__ uint32_t s2u(const void* p) {
    return (uint32_t)__cvta_generic_to_shared(p);
}
__device__ __forceinline__ void cp16(void* dst, const void* src) {
    asm volatile("cp.async.cg.shared.global [%0], [%1], 16;"
                 :: "r"(s2u(dst)), "l"(src));
}
__device__ __forceinline__ void cp_commit() { asm volatile("cp.async.commit_group;"); }
template<int N> __device__ __forceinline__ void cp_wait() {
    asm volatile("cp.async.wait_group %0;" :: "n"(N));
}
__device__ __forceinline__ void ldsm4(uint32_t* r, uint32_t addr) {
    asm volatile("ldmatrix.sync.aligned.m8n8.x4.shared.b16 {%0,%1,%2,%3}, [%4];"
                 : "=r"(r[0]), "=r"(r[1]), "=r"(r[2]), "=r"(r[3]) : "r"(addr));
}
// fp32-accumulate m16n8k16 (the proven fast path on this chip)
__device__ __forceinline__ void mma_f16(float* d, const uint32_t* a, const uint32_t* b) {
    asm volatile(
        "mma.sync.aligned.m16n8k16.row.col.f32.f16.f16.f32 "
        "{%0,%1,%2,%3},{%4,%5,%6,%7},{%8,%9},{%0,%1,%2,%3};"
        : "+f"(d[0]), "+f"(d[1]), "+f"(d[2]), "+f"(d[3])
        : "r"(a[0]), "r"(a[1]), "r"(a[2]), "r"(a[3]), "r"(b[0]), "r"(b[1]));
}

// ---------------------------------------------------------------------------
// Consolidated prep (round-8 block map, vectorized tiles).
// 32x32 transpose tile, 256 threads: float4 loads, uint2 fp16 stores.
// Store-phase smem banks: addr=(4q+i)*33+n -> bank (4q+n+i)%32, conflict-free.
// ---------------------------------------------------------------------------
__device__ __forceinline__ void tr_tile(const float* __restrict__ W,
                                        __half* __restrict__ WT,
                                        int K, int N, int kt, int nt, int tid) {
    __shared__ float t[32][33];
    const int k0 = kt * 32, n0 = nt * 32;
    {
        int r = tid >> 3, c = (tid & 7) * 4;
        float4 v = *(const float4*)(W + (size_t)(k0 + r) * N + n0 + c);
        t[r][c] = v.x; t[r][c + 1] = v.y; t[r][c + 2] = v.z; t[r][c + 3] = v.w;
    }
    __syncthreads();
    {
        int n = tid >> 3, q = (tid & 7) * 4;
        __half2 h0 = __floats2half2_rn(t[q][n],     t[q + 1][n]);
        __half2 h1 = __floats2half2_rn(t[q + 2][n], t[q + 3][n]);
        *(uint2*)(WT + (size_t)(n0 + n) * K + k0 + q) =
            make_uint2(*(uint32_t*)&h0, *(uint32_t*)&h1);
    }
}

__global__ void __launch_bounds__(256) k_prep(
    const float* __restrict__ state,
    const float* __restrict__ W1, const float* __restrict__ W2,
    const float* __restrict__ Wf, const float* __restrict__ Wg,
    const float* __restrict__ bg, const float* __restrict__ bf)
{
    const int id = blockIdx.x, tid = threadIdx.x;
    if (id < 2048) {
        tr_tile(Wg, g_WgT, K_CAT, N_G, id & 63, id >> 6, tid);
    } else if (id < 2176) {
        int t = id - 2048;
        tr_tile(Wf, g_WfT, K_CAT, N_F, t & 63, t >> 6, tid);
    } else if (id < 2304) {
        int t = id - 2176;
        int e = t >> 4; t &= 15;
        tr_tile(W1 + (size_t)e * S_DIM * H_DIM,
                g_W1T + (size_t)e * S_DIM * H_DIM,
                S_DIM, H_DIM, t & 1, t >> 1, tid);
    } else if (id < 2816) {
        int t = id - 2304;
        int e = t >> 6; t &= 63;
        tr_tile(W2 + (size_t)e * H_DIM * H_DIM,
                g_W2T + (size_t)e * H_DIM * H_DIM,
                H_DIM, H_DIM, t & 7, t >> 3, tid);
    } else if (id < 3840) {
        size_t i = ((size_t)(id - 2816) * 256 + tid) * 4;
        float4 v = *(const float4*)(state + i);
        __half2 h0 = __floats2half2_rn(v.x, v.y);
        __half2 h1 = __floats2half2_rn(v.z, v.w);
        *(uint2*)(g_Sh + i) = make_uint2(*(uint32_t*)&h0, *(uint32_t*)&h1);
    } else {
        int q = (id - 3840) * 256 + tid;
        if (q < N_G) {
            float s = 0.f;
            #pragma unroll
            for (int e = 0; e < E_DIM; ++e) s += bg[(size_t)e * N_G + q];
            g_bsum[q] = s;
        } else if (q < N_G + N_F) {
            int qq = q - N_G;
            float s = 0.f;
            #pragma unroll
            for (int e = 0; e < E_DIM; ++e) s += bf[(size_t)e * N_F + qq];
            g_bsum[q] = s;
        }
    }
}

// ---------------------------------------------------------------------------
// Pass 1 (round-8 proven): CTA = (64 batch rows, member e), 128 threads /
// 4 warps, warp tile 64x64, fp32-acc MMA, 2 CTAs/SM.
// ---------------------------------------------------------------------------
__global__ void __launch_bounds__(128, 2) k_mlp(
    const float* __restrict__ b1, const float* __restrict__ b2)
{
    extern __shared__ __half smh[];
    __half* sS   = smh;                  // [64][72] phase 1
    __half* sW1  = smh + 64 * 72;        // [256][72] phase 1
    __half* sH   = smh;                  // [64][264] phase 2 (aliases sS/sW1)
    __half* sW2a = smh + 23040;          // [256][40]
    __half* sW2b = sW2a + 256 * 40;      // [256][40]

    const int tid = threadIdx.x;
    const int lane = tid & 31, wn = tid >> 5;
    const int g = lane >> 2, tg = lane & 3;
    const int mi = lane >> 3, ri = lane & 7;
    const int b0 = blockIdx.x * 64;
    const int e  = blockIdx.y;

    const __half* W1e = g_W1T + (size_t)e * H_DIM * S_DIM;
    const __half* W2e = g_W2T + (size_t)e * H_DIM * H_DIM;

    auto loadW2 = [&](__half* buf, int kc) {
        #pragma unroll
        for (int j = 0; j < 8; ++j) {
            int lin = j * 128 + tid, row = lin >> 2, seg = lin & 3;
            cp16(buf + row * 40 + seg * 8, W2e + (size_t)row * 256 + kc * 32 + seg * 8);
        }
    };

    #pragma unroll
    for (int j = 0; j < 4; ++j) {
        int lin = j * 128 + tid, row = lin >> 3, seg = lin & 7;
        cp16(sS + row * 72 + seg * 8, g_Sh + (size_t)(b0 + row) * S_DIM + seg * 8);
    }
    #pragma unroll
    for (int j = 0; j < 16; ++j) {
        int lin = j * 128 + tid, row = lin >> 3, seg = lin & 7;
        cp16(sW1 + row * 72 + seg * 8, W1e + (size_t)row * S_DIM + seg * 8);
    }
    cp_commit();
    loadW2(sW2a, 0); cp_commit();
    loadW2(sW2b, 1); cp_commit();
    cp_wait<2>(); __syncthreads();

    const uint32_t uS = s2u(sS), uW1 = s2u(sW1);
    const uint32_t uH = s2u(sH), uW2 = s2u(sW2a);
    uint32_t aoff72[4], aoff264[4], boff72[4], boff40[4];
    #pragma unroll
    for (int t = 0; t < 4; ++t) {
        int rrow = t * 16 + ri + (mi & 1) * 8;
        int kadd = (mi >> 1) * 8;
        aoff72[t]  = (uint32_t)(rrow * 72  + kadd) * 2;
        aoff264[t] = (uint32_t)(rrow * 264 + kadd) * 2;
    }
    #pragma unroll
    for (int j = 0; j < 4; ++j) {
        int nrow = wn * 64 + (j * 2 + (lane >> 4)) * 8 + ri;
        int kadd = ((lane >> 3) & 1) * 8;
        boff72[j] = (uint32_t)(nrow * 72 + kadd) * 2;
        boff40[j] = (uint32_t)(nrow * 40 + kadd) * 2;
    }

    float acc[4][8][4];
    #pragma unroll
    for (int t = 0; t < 4; ++t)
        #pragma unroll
        for (int u = 0; u < 8; ++u)
            #pragma unroll
            for (int v = 0; v < 4; ++v) acc[t][u][v] = 0.f;

    #pragma unroll
    for (int ks = 0; ks < 4; ++ks) {
        uint32_t a[4][4], b[8][2];
        #pragma unroll
        for (int t = 0; t < 4; ++t) ldsm4(a[t], uS + aoff72[t] + ks * 32);
        #pragma unroll
        for (int j = 0; j < 4; ++j) {
            uint32_t r[4];
            ldsm4(r, uW1 + boff72[j] + ks * 32);
            b[2*j][0] = r[0]; b[2*j][1] = r[1];
            b[2*j+1][0] = r[2]; b[2*j+1][1] = r[3];
        }
        #pragma unroll
        for (int t = 0; t < 4; ++t)
            #pragma unroll
            for (int u = 0; u < 8; ++u)
                mma_f16(acc[t][u], a[t], b[u]);
    }
    __syncthreads();

    #pragma unroll
    for (int t = 0; t < 4; ++t) {
        int r = t * 16 + g;
        #pragma unroll
        for (int u = 0; u < 8; ++u) {
            int cl = wn * 64 + u * 8 + tg * 2;
            float bb0 = b1[(size_t)e * H_DIM + cl];
            float bb1 = b1[(size_t)e * H_DIM + cl + 1];
            __half2 v0 = __floats2half2_rn(tanhf(acc[t][u][0] + bb0),
                                           tanhf(acc[t][u][1] + bb1));
            __half2 v1 = __floats2half2_rn(tanhf(acc[t][u][2] + bb0),
                                           tanhf(acc[t][u][3] + bb1));
            *(__half2*)(sH + r * 264 + cl)       = v0;
            *(__half2*)(sH + (r + 8) * 264 + cl) = v1;
        }
    }
    __syncthreads();

    #pragma unroll
    for (int t = 0; t < 4; ++t)
        #pragma unroll
        for (int u = 0; u < 8; ++u)
            #pragma unroll
            for (int v = 0; v < 4; ++v) acc[t][u][v] = 0.f;

    for (int kc = 0; kc < 8; ++kc) {
        if (kc < 7) cp_wait<1>(); else cp_wait<0>();
        __syncthreads();
        const uint32_t stB = uW2 + (uint32_t)(kc & 1) * (256 * 40 * 2);
        #pragma unroll
        for (int ks = 0; ks < 2; ++ks) {
            const uint32_t kbyteA = (uint32_t)(kc * 32 + ks * 16) * 2;
            uint32_t a[4][4], b[8][2];
            #pragma unroll
            for (int t = 0; t < 4; ++t) ldsm4(a[t], uH + aoff264[t] + kbyteA);
            #pragma unroll
            for (int j = 0; j < 4; ++j) {
                uint32_t r[4];
                ldsm4(r, stB + boff40[j] + ks * 32);
                b[2*j][0] = r[0]; b[2*j][1] = r[1];
                b[2*j+1][0] = r[2]; b[2*j+1][1] = r[3];
            }
            #pragma unroll
            for (int t = 0; t < 4; ++t)
                #pragma unroll
                for (int u = 0; u < 8; ++u)
                    mma_f16(acc[t][u], a[t], b[u]);
        }
        __syncthreads();
        if (kc + 2 < 8) {
            loadW2((kc & 1) ? sW2b : sW2a, kc + 2);
            cp_commit();
        }
    }

    #pragma unroll
    for (int t = 0; t < 4; ++t) {
        size_t r = (size_t)b0 + t * 16 + g;
        #pragma unroll
        for (int u = 0; u < 8; ++u) {
            int cl = wn * 64 + u * 8 + tg * 2;
            float bb0 = b2[(size_t)e * H_DIM + cl];
            float bb1 = b2[(size_t)e * H_DIM + cl + 1];
            __half2 v0 = __floats2half2_rn(tanhf(acc[t][u][0] + bb0),
                                           tanhf(acc[t][u][1] + bb1));
            __half2 v1 = __floats2half2_rn(tanhf(acc[t][u][2] + bb0),
                                           tanhf(acc[t][u][3] + bb1));
            __half* dst = g_H + r * K_CAT + e * H_DIM + cl;
            *(__half2*)dst = v0;
            *(__half2*)(dst + 8 * K_CAT) = v1;
        }
    }
}

// ---------------------------------------------------------------------------
// Pass 2 tile worker (round-8 proven): fp32-acc HMMA, 3-stage cp.async,
// one __syncthreads per K-chunk.
// ---------------------------------------------------------------------------
template<int NT>
__device__ __forceinline__ void gemm_tile(
    const __half* __restrict__ Abase, const __half* __restrict__ Bbase,
    const float* __restrict__ bsumN, float* __restrict__ outBase, int Ntot,
    __half* smh, int tid)
{
    constexpr int TN  = NT * 16;
    constexpr int NCH = K_CAT / 64;

    __half* sA = smh;
    __half* sB = smh + 3 * 128 * 72;
    float*  sBias = (float*)(sB + 3 * TN * 72);

    const int lane = tid & 31, w = tid >> 5;
    const int wm = w >> 1, wn = w & 1;
    const int g = lane >> 2, tg = lane & 3;
    const int mi = lane >> 3, ri = lane & 7;

    if (tid < TN) sBias[tid] = bsumN[tid];

    auto loadA = [&](int stage, int kc) {
        __half* buf = sA + stage * (128 * 72);
        #pragma unroll
        for (int j = 0; j < 8; ++j) {
            int lin = j * 128 + tid, row = lin >> 3, seg = lin & 7;
            cp16(buf + row * 72 + seg * 8, Abase + (size_t)row * K_CAT + kc * 64 + seg * 8);
        }
    };
    auto loadB = [&](int stage, int kc) {
        __half* buf = sB + stage * (TN * 72);
        #pragma unroll
        for (int j = 0; j < TN / 16; ++j) {
            int lin = j * 128 + tid, row = lin >> 3, seg = lin & 7;
            cp16(buf + row * 72 + seg * 8, Bbase + (size_t)row * K_CAT + kc * 64 + seg * 8);
        }
    };

    const uint32_t uA = s2u(sA), uB = s2u(sB);
    uint32_t aoff[4], boff[NT / 2];
    #pragma unroll
    for (int t = 0; t < 4; ++t)
        aoff[t] = (uint32_t)((wm * 64 + t * 16 + ri + (mi & 1) * 8) * 72 +
                             (mi >> 1) * 8) * 2;
    #pragma unroll
    for (int j = 0; j < NT / 2; ++j)
        boff[j] = (uint32_t)((wn * (TN / 2) + (j * 2 + (lane >> 4)) * 8 + ri) * 72 +
                             ((lane >> 3) & 1) * 8) * 2;

    float acc[4][NT][4];
    #pragma unroll
    for (int t = 0; t < 4; ++t)
        #pragma unroll
        for (int u = 0; u < NT; ++u)
            #pragma unroll
            for (int v = 0; v < 4; ++v) acc[t][u][v] = 0.f;

    loadA(0, 0); loadB(0, 0); cp_commit();
    loadA(1, 1); loadB(1, 1); cp_commit();

    for (int kc = 0; kc < NCH; ++kc) {
        if (kc + 1 < NCH) cp_wait<1>(); else cp_wait<0>();
        __syncthreads();
        if (kc + 2 < NCH) {
            loadA((kc + 2) % 3, kc + 2);
            loadB((kc + 2) % 3, kc + 2);
            cp_commit();
        }
        const int stage = kc % 3;
        const uint32_t stA = uA + (uint32_t)stage * (128 * 72 * 2);
        const uint32_t stB = uB + (uint32_t)stage * (TN * 72 * 2);

        #pragma unroll
        for (int ks = 0; ks < 4; ++ks) {
            uint32_t a[4][4], b[NT][2];
            #pragma unroll
            for (int t = 0; t < 4; ++t) ldsm4(a[t], stA + aoff[t] + ks * 32);
            #pragma unroll
            for (int j = 0; j < NT / 2; ++j) {
                uint32_t r[4];
                ldsm4(r, stB + boff[j] + ks * 32);
                b[2*j][0] = r[0]; b[2*j][1] = r[1];
                b[2*j+1][0] = r[2]; b[2*j+1][1] = r[3];
            }
            #pragma unroll
            for (int t = 0; t < 4; ++t)
                #pragma unroll
                for (int u = 0; u < NT; ++u)
                    mma_f16(acc[t][u], a[t], b[u]);
        }
    }

    #pragma unroll
    for (int t = 0; t < 4; ++t) {
        size_t r0 = wm * 64 + t * 16 + g;
        #pragma unroll
        for (int u = 0; u < NT; ++u) {
            int cl = wn * (TN / 2) + u * 8 + tg * 2;
            float bs0 = sBias[cl], bs1 = sBias[cl + 1];
            float2 v0, v1;
            v0.x = 0.125f * (acc[t][u][0] + bs0);
            v0.y = 0.125f * (acc[t][u][1] + bs1);
            v1.x = 0.125f * (acc[t][u][2] + bs0);
            v1.y = 0.125f * (acc[t][u][3] + bs1);
            *(float2*)(outBase + r0 * Ntot + cl)       = v0;
            *(float2*)(outBase + (r0 + 8) * Ntot + cl) = v1;
        }
    }
}

// Merged output GEMM, round-8 ordering: g tiles ids 0..1023, f tiles last.
__global__ void __launch_bounds__(128, 2) k_out(
    float* __restrict__ out_f, float* __restrict__ out_g)
{
    extern __shared__ __half smh[];
    const int id = blockIdx.x, tid = threadIdx.x;
    if (id < 1024) {
        const int bm = id & 127, bn = id >> 7;
        gemm_tile<8>(g_H + (size_t)bm * 128 * K_CAT,
                     g_WgT + (size_t)bn * 128 * K_CAT,
                     g_bsum + bn * 128,
                     out_g + (size_t)bm * 128 * N_G + bn * 128,
                     N_G, smh, tid);
    } else {
        const int bm = id - 1024;
        gemm_tile<4>(g_H + (size_t)bm * 128 * K_CAT,
                     g_WfT,
                     g_bsum + N_G,
                     out_f + (size_t)bm * 128 * N_F,
                     N_F, smh, tid);
    }
}

// ---------------------------------------------------------------------------
extern "C" void kernel_launch(void* const* d_in, const int* in_sizes, int n_in,
                              void* d_out, int out_size)
{
    const float* state = (const float*)d_in[0];
    const float* W1    = (const float*)d_in[1];
    const float* b1    = (const float*)d_in[2];
    const float* W2    = (const float*)d_in[3];
    const float* b2    = (const float*)d_in[4];
    const float* Wf    = (const float*)d_in[5];
    const float* bf    = (const float*)d_in[6];
    const float* Wg    = (const float*)d_in[7];
    const float* bg    = (const float*)d_in[8];

    float* out   = (float*)d_out;
    float* out_f = out;                              // f_mean [B, 64]
    float* out_g = out + (size_t)B_DIM * S_DIM;      // g_mean [B, 1024]

    const int smemM = 23040 * 2 + 2 * 256 * 40 * 2;            // 87,040 B
    const int smemO = (3 * 128 * 72 + 3 * 128 * 72) * 2 + 512; // 111,104 B

    cudaFuncSetAttribute(k_mlp, cudaFuncAttributeMaxDynamicSharedMemorySize, smemM);
    cudaFuncSetAttribute(k_out, cudaFuncAttributeMaxDynamicSharedMemorySize, smemO);

    k_prep<<<3845, 256>>>(state, W1, W2, Wf, Wg, bg, bf);
    k_mlp<<<dim3(B_DIM / 64, E_DIM), 128, smemM>>>(b1, b2);
    k_out<<<1152, 128, smemO>>>(out_f, out_g);
}